// round 1
// baseline (speedup 1.0000x reference)
#include <cuda_runtime.h>

#define BB 2048
#define NN 64
#define DD 512
#define HH 8
#define HDD 64
#define LL 3
#define FFD 2048
#define RR 400

// ---------------- scratch (device globals; no allocations allowed) ----------------
__device__ float g_pre[BB * NN * DD];          // e@W2 + rW1[nbr_r] + msg_b   (268 MB)
__device__ float g_rW1[RR * DD];               // emb_r @ W1
__device__ float g_Khat[LL * HH * RR * HDD];   // (emb_r @ Wk[l,h]) + bk
__device__ float g_h[BB * DD];
__device__ float g_embq[BB * DD];
__device__ float g_hW0[BB * DD];
__device__ float g_qh[BB * DD];                // [B, H*HD]
__device__ float g_ctx[BB * HH * DD];          // [B, H, D]
__device__ float g_x[BB * DD];
__device__ float g_ff[BB * FFD];

// ---------------- generic tiled fp32 GEMM ----------------
// C[m, n] (per z-slice) = act( sum_k A[row(m), z, k] * B_z[k, n] + bias_z[n] + rowadd[idx2(m), n] )
// BM=BN=64, BK=16, 256 threads, 4x4 per-thread microtile.
__global__ void __launch_bounds__(256) gemm_k(
    const float* __restrict__ A, int a_row_stride, int a_head_off,
    const int* __restrict__ a_gidx,
    const float* __restrict__ Bm, int ldb, int b_head_stride,
    const float* __restrict__ bias, int bias_head_stride,
    const float* __restrict__ rowadd, const int* __restrict__ ra_gidx,
    float* __restrict__ C, int ldc, long long c_slice_off,
    int M, int K, int act)
{
    __shared__ __align__(16) float As[16 * 68];  // [k][m], padded stride 68 (16B-aligned rows)
    __shared__ __align__(16) float Bs[16 * 64];  // [k][n]

    const int tid = threadIdx.x;
    const int tx = tid & 15, ty = tid >> 4;
    const int m0 = blockIdx.y * 64;
    const int n0 = blockIdx.x * 64;
    const int z  = blockIdx.z;

    const float* Bp = Bm + (size_t)z * b_head_stride;

    float acc[4][4];
#pragma unroll
    for (int i = 0; i < 4; i++)
#pragma unroll
        for (int j = 0; j < 4; j++) acc[i][j] = 0.f;

    // A load descriptors: element e = i*256+tid -> m = e>>4, k = e&15
    const float* ap[4];
    int am[4], ak[4];
#pragma unroll
    for (int i = 0; i < 4; i++) {
        int e = i * 256 + tid;
        am[i] = e >> 4;
        ak[i] = e & 15;
        int mrow = m0 + am[i];
        int r = (mrow < M) ? (a_gidx ? a_gidx[mrow] : mrow) : 0;
        ap[i] = A + (size_t)r * a_row_stride + (size_t)z * a_head_off + ak[i];
    }
    // B load descriptors: element e -> n = e&63, k = e>>6
    const float* bp[4];
    int bn[4], bkk[4];
#pragma unroll
    for (int i = 0; i < 4; i++) {
        int e = i * 256 + tid;
        bn[i]  = e & 63;
        bkk[i] = e >> 6;
        bp[i]  = Bp + (size_t)bkk[i] * ldb + n0 + bn[i];
    }
    const size_t bstep = (size_t)16 * ldb;

    const int ktiles = K >> 4;
    for (int t = 0; t < ktiles; t++) {
        float av[4], bv[4];
#pragma unroll
        for (int i = 0; i < 4; i++) { av[i] = ap[i][0]; ap[i] += 16; }
#pragma unroll
        for (int i = 0; i < 4; i++) { bv[i] = bp[i][0]; bp[i] += bstep; }
        __syncthreads();
#pragma unroll
        for (int i = 0; i < 4; i++) As[ak[i] * 68 + am[i]] = av[i];
#pragma unroll
        for (int i = 0; i < 4; i++) Bs[bkk[i] * 64 + bn[i]] = bv[i];
        __syncthreads();
#pragma unroll
        for (int kk = 0; kk < 16; kk++) {
            float4 a = *(const float4*)&As[kk * 68 + ty * 4];
            float4 b = *(const float4*)&Bs[kk * 64 + tx * 4];
            acc[0][0] += a.x * b.x; acc[0][1] += a.x * b.y; acc[0][2] += a.x * b.z; acc[0][3] += a.x * b.w;
            acc[1][0] += a.y * b.x; acc[1][1] += a.y * b.y; acc[1][2] += a.y * b.z; acc[1][3] += a.y * b.w;
            acc[2][0] += a.z * b.x; acc[2][1] += a.z * b.y; acc[2][2] += a.z * b.z; acc[2][3] += a.z * b.w;
            acc[3][0] += a.w * b.x; acc[3][1] += a.w * b.y; acc[3][2] += a.w * b.z; acc[3][3] += a.w * b.w;
        }
    }

    // epilogue
    const float* biasp = bias ? (bias + (size_t)z * bias_head_stride) : nullptr;
    float bcol[4];
#pragma unroll
    for (int j = 0; j < 4; j++) bcol[j] = biasp ? biasp[n0 + tx * 4 + j] : 0.f;

    float* Cp = C + (size_t)c_slice_off * z;
#pragma unroll
    for (int i = 0; i < 4; i++) {
        int m = m0 + ty * 4 + i;
        if (m < M) {
            float ra[4] = {0.f, 0.f, 0.f, 0.f};
            if (rowadd) {
                const float* rp = rowadd + (size_t)ra_gidx[m] * DD + n0 + tx * 4;
#pragma unroll
                for (int j = 0; j < 4; j++) ra[j] = rp[j];
            }
            float4 o;
            o.x = acc[i][0] + bcol[0] + ra[0];
            o.y = acc[i][1] + bcol[1] + ra[1];
            o.z = acc[i][2] + bcol[2] + ra[2];
            o.w = acc[i][3] + bcol[3] + ra[3];
            if (act == 1) {
                o.x = fmaxf(o.x, 0.f); o.y = fmaxf(o.y, 0.f);
                o.z = fmaxf(o.z, 0.f); o.w = fmaxf(o.w, 0.f);
            }
            *(float4*)&Cp[(size_t)m * ldc + n0 + tx * 4] = o;
        }
    }
}

// ---------------- fused attention (one CTA per batch row; warp == head) ----------------
__global__ void __launch_bounds__(256) attn_k(
    const float* __restrict__ qh, const float* __restrict__ Khat,  // Khat: [H, R, HD] (this layer)
    const int* __restrict__ nbr_r, const float* __restrict__ masks,
    const float* __restrict__ hW0, const float* __restrict__ pre,
    float* __restrict__ ctx)
{
    const int b = blockIdx.x;
    const int tid = threadIdx.x;
    const int lane = tid & 31, w = tid >> 5;  // warp w handles head w

    __shared__ float s_q[HH * HDD];
    __shared__ float s_attn[HH * NN];
    __shared__ int   s_nbr[NN];

    s_q[tid]       = qh[(size_t)b * DD + tid];
    s_q[tid + 256] = qh[(size_t)b * DD + tid + 256];
    if (tid < NN) s_nbr[tid] = nbr_r[b * NN + tid];
    __syncthreads();

    // scores
    {
        float q0 = s_q[w * 64 + lane], q1 = s_q[w * 64 + lane + 32];
        for (int n = 0; n < NN; n++) {
            int j = s_nbr[n];
            const float* kr = Khat + ((size_t)w * RR + j) * HDD;
            float p = q0 * kr[lane] + q1 * kr[lane + 32];
#pragma unroll
            for (int o = 16; o; o >>= 1) p += __shfl_xor_sync(0xffffffffu, p, o);
            if (lane == 0)
                s_attn[w * 64 + n] = p * 0.125f - 1e31f * (1.0f - masks[b * NN + n]);
        }
    }
    __syncwarp();
    // softmax per head
    {
        float s0 = s_attn[w * 64 + lane], s1 = s_attn[w * 64 + lane + 32];
        float m = fmaxf(s0, s1);
#pragma unroll
        for (int o = 16; o; o >>= 1) m = fmaxf(m, __shfl_xor_sync(0xffffffffu, m, o));
        float e0 = expf(s0 - m), e1 = expf(s1 - m);
        float sum = e0 + e1;
#pragma unroll
        for (int o = 16; o; o >>= 1) sum += __shfl_xor_sync(0xffffffffu, sum, o);
        float inv = 1.f / sum;
        s_attn[w * 64 + lane]      = e0 * inv;
        s_attn[w * 64 + lane + 32] = e1 * inv;
    }
    __syncthreads();

    // ctx[b,h,:] = sum_n attn[h,n] * leaky(hW0[b,:] + pre[b,n,:])
    const float hw0a = hW0[(size_t)b * DD + tid];
    const float hw0b = hW0[(size_t)b * DD + tid + 256];
    float acc[HH][2];
#pragma unroll
    for (int hh = 0; hh < HH; hh++) { acc[hh][0] = 0.f; acc[hh][1] = 0.f; }

    const float* prow = pre + (size_t)b * NN * DD;
    for (int n = 0; n < NN; n++) {
        float v0 = hw0a + prow[(size_t)n * DD + tid];
        float v1 = hw0b + prow[(size_t)n * DD + tid + 256];
        v0 = (v0 > 0.f) ? v0 : 0.01f * v0;
        v1 = (v1 > 0.f) ? v1 : 0.01f * v1;
#pragma unroll
        for (int hh = 0; hh < HH; hh++) {
            float a = s_attn[hh * 64 + n];
            acc[hh][0] += a * v0;
            acc[hh][1] += a * v1;
        }
    }
#pragma unroll
    for (int hh = 0; hh < HH; hh++) {
        ctx[((size_t)b * HH + hh) * DD + tid]       = acc[hh][0];
        ctx[((size_t)b * HH + hh) * DD + tid + 256] = acc[hh][1];
    }
}

// ---------------- layernorm: h = LN(h + x) * g + b  (biased var, eps 1e-5) ----------------
__global__ void __launch_bounds__(128) ln_k(
    float* __restrict__ h, const float* __restrict__ x,
    const float* __restrict__ gamma, const float* __restrict__ beta)
{
    const int b = blockIdx.x, tid = threadIdx.x;
    __shared__ float sred[8];
    float4 hv = ((const float4*)(h + (size_t)b * DD))[tid];
    float4 xv = ((const float4*)(x + (size_t)b * DD))[tid];
    float v0 = hv.x + xv.x, v1 = hv.y + xv.y, v2 = hv.z + xv.z, v3 = hv.w + xv.w;

    float s = v0 + v1 + v2 + v3;
#pragma unroll
    for (int o = 16; o; o >>= 1) s += __shfl_xor_sync(0xffffffffu, s, o);
    if ((tid & 31) == 0) sred[tid >> 5] = s;
    __syncthreads();
    float mean = (sred[0] + sred[1] + sred[2] + sred[3]) * (1.f / 512.f);

    v0 -= mean; v1 -= mean; v2 -= mean; v3 -= mean;
    float sq = v0 * v0 + v1 * v1 + v2 * v2 + v3 * v3;
#pragma unroll
    for (int o = 16; o; o >>= 1) sq += __shfl_xor_sync(0xffffffffu, sq, o);
    if ((tid & 31) == 0) sred[4 + (tid >> 5)] = sq;
    __syncthreads();
    float var = (sred[4] + sred[5] + sred[6] + sred[7]) * (1.f / 512.f);
    float rstd = rsqrtf(var + 1e-5f);

    float4 g = ((const float4*)gamma)[tid];
    float4 be = ((const float4*)beta)[tid];
    float4 o;
    o.x = v0 * rstd * g.x + be.x;
    o.y = v1 * rstd * g.y + be.y;
    o.z = v2 * rstd * g.z + be.z;
    o.w = v3 * rstd * g.w + be.w;
    ((float4*)(h + (size_t)b * DD))[tid] = o;
}

// ---------------- init: gather h = emb_e[e1], embq = emb_r[q]; write emb_q output half ----------------
__global__ void __launch_bounds__(128) init_k(
    const int* __restrict__ e1, const int* __restrict__ qi,
    const float* __restrict__ emb_e, const float* __restrict__ emb_r,
    float* __restrict__ h, float* __restrict__ embq,
    float* __restrict__ outq, int writeq)
{
    const int b = blockIdx.x, t = threadIdx.x;
    const float* se = emb_e + (size_t)e1[b] * DD;
    const float* sr = emb_r + (size_t)qi[b] * DD;
    for (int j = t; j < DD; j += 128) {
        h[(size_t)b * DD + j] = se[j];
        float q = sr[j];
        embq[(size_t)b * DD + j] = q;
        if (writeq) outq[(size_t)b * DD + j] = q;
    }
}

__global__ void copy_k(float* __restrict__ out, const float* __restrict__ in)
{
    int i = blockIdx.x * 256 + threadIdx.x;
    out[i] = in[i];
}

// ---------------- launch ----------------
extern "C" void kernel_launch(void* const* d_in, const int* in_sizes, int n_in,
                              void* d_out, int out_size)
{
    const int*   e1    = (const int*)d_in[0];
    const int*   qidx  = (const int*)d_in[1];
    const int*   nbr_r = (const int*)d_in[2];
    const int*   nbr_e = (const int*)d_in[3];
    const float* masks = (const float*)d_in[4];
    const float* emb_e = (const float*)d_in[5];
    const float* emb_r = (const float*)d_in[6];
    const float* msg_W = (const float*)d_in[7];
    const float* msg_b = (const float*)d_in[8];
    const float* Wq    = (const float*)d_in[9];
    const float* bq    = (const float*)d_in[10];
    const float* Wk    = (const float*)d_in[11];
    const float* bk    = (const float*)d_in[12];
    const float* Wv    = (const float*)d_in[13];
    const float* bv    = (const float*)d_in[14];
    const float* ffW1  = (const float*)d_in[15];
    const float* ffb1  = (const float*)d_in[16];
    const float* ffW2  = (const float*)d_in[17];
    const float* ffb2  = (const float*)d_in[18];
    const float* ln1g  = (const float*)d_in[19];
    const float* ln1b  = (const float*)d_in[20];
    const float* ln2g  = (const float*)d_in[21];
    const float* ln2b  = (const float*)d_in[22];
    float* out = (float*)d_out;

    float *p_pre, *p_rW1, *p_Khat, *p_h, *p_embq, *p_hW0, *p_qh, *p_ctx, *p_x, *p_ff;
    cudaGetSymbolAddress((void**)&p_pre,  g_pre);
    cudaGetSymbolAddress((void**)&p_rW1,  g_rW1);
    cudaGetSymbolAddress((void**)&p_Khat, g_Khat);
    cudaGetSymbolAddress((void**)&p_h,    g_h);
    cudaGetSymbolAddress((void**)&p_embq, g_embq);
    cudaGetSymbolAddress((void**)&p_hW0,  g_hW0);
    cudaGetSymbolAddress((void**)&p_qh,   g_qh);
    cudaGetSymbolAddress((void**)&p_ctx,  g_ctx);
    cudaGetSymbolAddress((void**)&p_x,    g_x);
    cudaGetSymbolAddress((void**)&p_ff,   g_ff);

    int writeq = (out_size >= 2 * BB * DD) ? 1 : 0;
    init_k<<<BB, 128>>>(e1, qidx, emb_e, emb_r, p_h, p_embq, out + (size_t)BB * DD, writeq);

    // rW1[j,:] = emb_r[j] @ W1   (W1 = msg_W rows 512..1023)
    gemm_k<<<dim3(8, 7, 1), 256>>>(emb_r, DD, 0, nullptr,
                                   msg_W + 512 * 512, 512, 0,
                                   nullptr, 0, nullptr, nullptr,
                                   p_rW1, 512, 0, RR, 512, 0);
    // Khat[l,h,j,:] = emb_r[j] @ Wk[l,h] + bk[l,h]   (z = l*8+h)
    gemm_k<<<dim3(1, 7, LL * HH), 256>>>(emb_r, DD, 0, nullptr,
                                         Wk, 64, DD * HDD,
                                         bk, HDD, nullptr, nullptr,
                                         p_Khat, HDD, (long long)RR * HDD, RR, 512, 0);
    // pre[b,n,:] = emb_e[nbr_e[b,n]] @ W2 + msg_b + rW1[nbr_r[b,n]]
    gemm_k<<<dim3(8, 2048, 1), 256>>>(emb_e, DD, 0, nbr_e,
                                      msg_W + 1024 * 512, 512, 0,
                                      msg_b, 0, p_rW1, nbr_r,
                                      p_pre, 512, 0, BB * NN, 512, 0);

    for (int l = 0; l < LL; l++) {
        // hW0 = h @ W0
        gemm_k<<<dim3(8, 32, 1), 256>>>(p_h, DD, 0, nullptr,
                                        msg_W, 512, 0,
                                        nullptr, 0, nullptr, nullptr,
                                        p_hW0, 512, 0, BB, 512, 0);
        // qh[b, h*64+e] = embq @ Wq[l,h] + bq[l,h]   (z = head)
        gemm_k<<<dim3(1, 32, HH), 256>>>(p_embq, DD, 0, nullptr,
                                         Wq + (size_t)l * HH * DD * HDD, HDD, DD * HDD,
                                         bq + l * HH * HDD, HDD, nullptr, nullptr,
                                         p_qh, 512, 64, BB, 512, 0);
        // fused scores + softmax + ctx accumulation
        attn_k<<<BB, 256>>>(p_qh, p_Khat + (size_t)l * HH * RR * HDD,
                            nbr_r, masks, p_hW0, p_pre, p_ctx);
        // x[b, h*64+e] = ctx[b,h] @ Wv[l,h] + bv[l,h]
        gemm_k<<<dim3(1, 32, HH), 256>>>(p_ctx, HH * DD, DD, nullptr,
                                         Wv + (size_t)l * HH * DD * HDD, HDD, DD * HDD,
                                         bv + l * HH * HDD, HDD, nullptr, nullptr,
                                         p_x, 512, 64, BB, 512, 0);
        // h = LN1(h + x)
        ln_k<<<BB, 128>>>(p_h, p_x, ln1g + l * 512, ln1b + l * 512);
        // ff = relu(h @ ffW1 + b1)
        gemm_k<<<dim3(32, 32, 1), 256>>>(p_h, DD, 0, nullptr,
                                         ffW1 + (size_t)l * DD * FFD, FFD, 0,
                                         ffb1 + l * FFD, 0, nullptr, nullptr,
                                         p_ff, FFD, 0, BB, 512, 1);
        // x = ff @ ffW2 + b2
        gemm_k<<<dim3(8, 32, 1), 256>>>(p_ff, FFD, 0, nullptr,
                                        ffW2 + (size_t)l * FFD * DD, DD, 0,
                                        ffb2 + l * DD, 0, nullptr, nullptr,
                                        p_x, DD, 0, BB, 2048, 0);
        // h = LN2(h + x)
        ln_k<<<BB, 128>>>(p_h, p_x, ln2g + l * 512, ln2b + l * 512);
    }

    copy_k<<<(BB * DD) / 256, 256>>>(out, p_h);
}